// round 14
// baseline (speedup 1.0000x reference)
#include <cuda_runtime.h>
#include <cuda_bf16.h>
#include <cuda_fp16.h>
#include <math.h>
#include <stdint.h>

// Problem constants (fixed instance): N=50000, E=1600000, D=256, H=8, C=32.
#define DD 256
#define HH 8
#define CC 32
#define MAXN 50176          // 392 * 128
#define MAXE 1600000
#define SCAN_BLK 1024
#define MAXSB 64
#define NB 512              // total output cols (Wlin | Wres)

// ---------------- scratch (device globals; no allocation allowed) ----------
__device__ __half g_xh[MAXN * DD];           // x fp16 (message gather)
__device__ float g_al[MAXN * HH];
__device__ float g_ar[MAXN * HH];
__device__ int   g_cnt[MAXN + 1];
__device__ int   g_off[MAXN + 1];
__device__ int   g_cur[MAXN];
__device__ int2  g_edge[MAXE];               // dst-sorted payload: (src, w bits)
__device__ int   g_bsum[MAXSB];
__device__ int   g_bpre[MAXSB];
// bf16 hi/lo splits for tensor-core GEMM
__device__ __nv_bfloat16 g_ahi[MAXN * DD];
__device__ __nv_bfloat16 g_alo[MAXN * DD];
__device__ __nv_bfloat16 g_bhi[NB * DD];     // [n][k], k contiguous (W transposed)
__device__ __nv_bfloat16 g_blo[NB * DD];

// ---------------- helpers (baseline PTX, sm_80+) ---------------------------
__device__ __forceinline__ uint32_t s2u(const void* p) {
    uint32_t a;
    asm("{ .reg .u64 t; cvta.to.shared.u64 t, %1; cvt.u32.u64 %0, t; }"
        : "=r"(a) : "l"(p));
    return a;
}
__device__ __forceinline__ void ldsm4(uint32_t* r, uint32_t addr) {
    asm volatile("ldmatrix.sync.aligned.m8n8.x4.shared.b16 {%0,%1,%2,%3}, [%4];"
                 : "=r"(r[0]), "=r"(r[1]), "=r"(r[2]), "=r"(r[3]) : "r"(addr));
}
__device__ __forceinline__ void mma16816(float* d, const uint32_t* a,
                                         const uint32_t* b) {
    asm volatile(
        "mma.sync.aligned.m16n8k16.row.col.f32.bf16.bf16.f32 "
        "{%0,%1,%2,%3}, {%4,%5,%6,%7}, {%8,%9}, {%0,%1,%2,%3};"
        : "+f"(d[0]), "+f"(d[1]), "+f"(d[2]), "+f"(d[3])
        : "r"(a[0]), "r"(a[1]), "r"(a[2]), "r"(a[3]), "r"(b[0]), "r"(b[1]));
}
__device__ __forceinline__ void cpasync16(uint32_t dst, const void* src) {
    asm volatile("cp.async.ca.shared.global [%0], [%1], 16;"
                 :: "r"(dst), "l"(src));
}

// ---------------- K-1a: split feat into bf16 hi/lo + zero alpha ------------
__global__ void conv_feat(const float* __restrict__ feat, int N)
{
    int i = blockIdx.x * blockDim.x + threadIdx.x;       // float4 index
    if (i < N * HH) { g_al[i] = 0.f; g_ar[i] = 0.f; }
    if (i >= N * (DD / 4)) return;
    float4 v = ((const float4*)feat)[i];
    __nv_bfloat16 h0 = __float2bfloat16(v.x);
    __nv_bfloat16 h1 = __float2bfloat16(v.y);
    __nv_bfloat16 h2 = __float2bfloat16(v.z);
    __nv_bfloat16 h3 = __float2bfloat16(v.w);
    __nv_bfloat16 l0 = __float2bfloat16(v.x - __bfloat162float(h0));
    __nv_bfloat16 l1 = __float2bfloat16(v.y - __bfloat162float(h1));
    __nv_bfloat16 l2 = __float2bfloat16(v.z - __bfloat162float(h2));
    __nv_bfloat16 l3 = __float2bfloat16(v.w - __bfloat162float(h3));
    ((__nv_bfloat162*)g_ahi)[i * 2]     = __nv_bfloat162(h0, h1);
    ((__nv_bfloat162*)g_ahi)[i * 2 + 1] = __nv_bfloat162(h2, h3);
    ((__nv_bfloat162*)g_alo)[i * 2]     = __nv_bfloat162(l0, l1);
    ((__nv_bfloat162*)g_alo)[i * 2 + 1] = __nv_bfloat162(l2, l3);
}

// ---------------- K-1b: transpose+split W into B [n][k] bf16 hi/lo ---------
__global__ void conv_w(const float* __restrict__ Wlin, const float* __restrict__ Wres)
{
    int idx = blockIdx.x * blockDim.x + threadIdx.x;     // n*256 + k
    if (idx >= NB * DD) return;
    int n = idx >> 8, k = idx & 255;
    float v = (n < 256) ? Wlin[k * 256 + n] : Wres[k * 256 + (n - 256)];
    __nv_bfloat16 h = __float2bfloat16(v);
    __nv_bfloat16 l = __float2bfloat16(v - __bfloat162float(h));
    g_bhi[idx] = h;
    g_blo[idx] = l;
}

// ---------------- K0: HMMA dual GEMM, cp.async double-buffered,
//                  alpha_l/alpha_r fused into epilogue (bn<2) ---------------
#define LDS 80                     // bytes per smem row — conflict-free ldmatrix
#define TILEB (128 * LDS)          // 10240 B per tile
#define SMEM_GEMM (2 * 4 * TILEB)  // 81920 B (double buffer x 4 tiles)
extern __shared__ char smg[];
__global__ __launch_bounds__(256) void gemm_tc(
    float* __restrict__ Res, const float* __restrict__ attl,
    const float* __restrict__ attr, int M)
{
    uint32_t sb = s2u(smg);
    int tid = threadIdx.x;
    int wid = tid >> 5, lane = tid & 31;
    int wm = wid >> 1;          // 0..3 -> m offset wm*32
    int wn = wid & 1;           // 0..1 -> n offset wn*64
    int bm = blockIdx.x, bn = blockIdx.y;

    uint32_t offA = (uint32_t)((lane & 15) * LDS + (lane >> 4) * 16);
    uint32_t offB = (uint32_t)(((lane & 7) + ((lane >> 4) & 1) * 8) * LDS +
                               ((lane >> 3) & 1) * 16);

    const __nv_bfloat16* srcs[4] = {
        g_ahi + (size_t)bm * 128 * DD, g_alo + (size_t)bm * 128 * DD,
        g_bhi + (size_t)bn * 128 * DD, g_blo + (size_t)bn * 128 * DD};

    int r0 = (tid * 2) >> 2, s0 = (tid * 2) & 3;
    int r1 = (tid * 2 + 1) >> 2, s1 = (tid * 2 + 1) & 3;

    float acc[2][8][4];
    #pragma unroll
    for (int mt = 0; mt < 2; mt++)
        #pragma unroll
        for (int nt = 0; nt < 8; nt++)
            #pragma unroll
            for (int j = 0; j < 4; j++) acc[mt][nt][j] = 0.f;

    auto issue = [&](int kc, int b) {
        uint32_t bufb = sb + (uint32_t)b * 4 * TILEB;
        #pragma unroll
        for (int m = 0; m < 4; m++) {
            const __nv_bfloat16* P = srcs[m] + kc * 32;
            cpasync16(bufb + m * TILEB + r0 * LDS + s0 * 16,
                      P + (size_t)r0 * DD + s0 * 8);
            cpasync16(bufb + m * TILEB + r1 * LDS + s1 * 16,
                      P + (size_t)r1 * DD + s1 * 8);
        }
        asm volatile("cp.async.commit_group;" ::: "memory");
    };

    issue(0, 0);
    for (int kc = 0; kc < 8; kc++) {
        if (kc < 7) {
            issue(kc + 1, (kc + 1) & 1);
            asm volatile("cp.async.wait_group 1;" ::: "memory");
        } else {
            asm volatile("cp.async.wait_group 0;" ::: "memory");
        }
        __syncthreads();

        uint32_t bufb = sb + (uint32_t)(kc & 1) * 4 * TILEB;
        uint32_t aHi = bufb, aLo = bufb + TILEB;
        uint32_t bHi = bufb + 2 * TILEB, bLo = bufb + 3 * TILEB;

        #pragma unroll
        for (int ks = 0; ks < 2; ks++) {
            uint32_t kb = ks * 32;
            uint32_t ah[2][4], al[2][4];
            #pragma unroll
            for (int mt = 0; mt < 2; mt++) {
                uint32_t ro = (uint32_t)((wm * 32 + mt * 16) * LDS) + offA + kb;
                ldsm4(ah[mt], aHi + ro);
                ldsm4(al[mt], aLo + ro);
            }
            uint32_t bh[4][4], bl[4][4];
            #pragma unroll
            for (int np = 0; np < 4; np++) {
                uint32_t ro = (uint32_t)((wn * 64 + np * 16) * LDS) + offB + kb;
                ldsm4(bh[np], bHi + ro);
                ldsm4(bl[np], bLo + ro);
            }
            #pragma unroll
            for (int mt = 0; mt < 2; mt++)
                #pragma unroll
                for (int nt = 0; nt < 8; nt++) {
                    float* d = acc[mt][nt];
                    const uint32_t* Bh2 = &bh[nt >> 1][(nt & 1) * 2];
                    const uint32_t* Bl2 = &bl[nt >> 1][(nt & 1) * 2];
                    mma16816(d, ah[mt], Bh2);
                    mma16816(d, ah[mt], Bl2);
                    mma16816(d, al[mt], Bh2);
                }
        }
        __syncthreads();
    }

    // epilogue
    int colbase = bn * 128 + wn * 64 + (lane & 3) * 2;   // (mod 256 for x cols)
    #pragma unroll
    for (int mt = 0; mt < 2; mt++) {
        int row0 = bm * 128 + wm * 32 + mt * 16 + (lane >> 2);
        #pragma unroll
        for (int half = 0; half < 2; half++) {
            int row = row0 + half * 8;
            bool valid = (row < M);
            if (bn < 2) {
                // x path: fp16 shadow + fused alpha partial dot products
                __half* hb = g_xh + (size_t)row * DD + bn * 128;
                float pa0 = 0.f, pa1 = 0.f, pb0 = 0.f, pb1 = 0.f;
                int xcol = bn * 128 + wn * 64 + (lane & 3) * 2;
                #pragma unroll
                for (int nt = 0; nt < 8; nt++) {
                    float a0 = acc[mt][nt][half * 2];
                    float a1 = acc[mt][nt][half * 2 + 1];
                    if (valid)
                        *(__half2*)(hb + wn * 64 + nt * 8 + (lane & 3) * 2) =
                            __floats2half2_rn(a0, a1);
                    int c = xcol + nt * 8;
                    float wl0 = __ldg(attl + c), wl1 = __ldg(attl + c + 1);
                    float wr0 = __ldg(attr + c), wr1 = __ldg(attr + c + 1);
                    float dl = a0 * wl0 + a1 * wl1;
                    float dr = a0 * wr0 + a1 * wr1;
                    if (nt < 4) { pa0 += dl; pb0 += dr; }
                    else        { pa1 += dl; pb1 += dr; }
                }
                // reduce over lane&3 (quad shares the row)
                pa0 += __shfl_xor_sync(0xffffffffu, pa0, 1);
                pa0 += __shfl_xor_sync(0xffffffffu, pa0, 2);
                pa1 += __shfl_xor_sync(0xffffffffu, pa1, 1);
                pa1 += __shfl_xor_sync(0xffffffffu, pa1, 2);
                pb0 += __shfl_xor_sync(0xffffffffu, pb0, 1);
                pb0 += __shfl_xor_sync(0xffffffffu, pb0, 2);
                pb1 += __shfl_xor_sync(0xffffffffu, pb1, 1);
                pb1 += __shfl_xor_sync(0xffffffffu, pb1, 2);
                if (valid && (lane & 3) == 0) {
                    int hA = (bn * 128 + wn * 64) >> 5;   // first head of block
                    atomicAdd(&g_al[row * HH + hA], pa0);
                    atomicAdd(&g_al[row * HH + hA + 1], pa1);
                    atomicAdd(&g_ar[row * HH + hA], pb0);
                    atomicAdd(&g_ar[row * HH + hA + 1], pb1);
                }
            } else if (valid) {
                float* base = Res + (size_t)row * DD + (bn - 2) * 128;
                #pragma unroll
                for (int nt = 0; nt < 8; nt++) {
                    float2 v = make_float2(acc[mt][nt][half * 2],
                                           acc[mt][nt][half * 2 + 1]);
                    *(float2*)(base + wn * 64 + nt * 8 + (lane & 3) * 2) = v;
                }
            }
        }
    }
    (void)colbase;
}

// ---------------- K2a: zero histogram (head of edge stream) ----------------
__global__ void zero_cnt(int N)
{
    int i = blockIdx.x * blockDim.x + threadIdx.x;
    if (i <= N) g_cnt[i] = 0;
}

// ---------------- K2b: histogram of destination degrees --------------------
__global__ void hist_dst(const int* __restrict__ ei, int E)
{
    int e = blockIdx.x * blockDim.x + threadIdx.x;
    if (e >= E) return;
    atomicAdd(&g_cnt[ei[E + e]], 1);
}

// ---------------- K3a/b/c: 3-phase exclusive scan --------------------------
__global__ void scan_phase1(int N)
{
    __shared__ int wsum[8];
    int t = threadIdx.x;
    int base = blockIdx.x * SCAN_BLK + t * 4;
    int s = 0;
    #pragma unroll
    for (int j = 0; j < 4; j++) s += (base + j < N) ? g_cnt[base + j] : 0;
    #pragma unroll
    for (int off = 16; off; off >>= 1) s += __shfl_xor_sync(0xffffffffu, s, off);
    if ((t & 31) == 0) wsum[t >> 5] = s;
    __syncthreads();
    if (t == 0) {
        int tot = 0;
        #pragma unroll
        for (int i = 0; i < 8; i++) tot += wsum[i];
        g_bsum[blockIdx.x] = tot;
    }
}
__global__ void scan_phase2(int nb)
{
    __shared__ int wt[2];
    int t = threadIdx.x;
    int lane = t & 31, wid = t >> 5;
    int mine = (t < nb) ? g_bsum[t] : 0;
    int v = mine;
    #pragma unroll
    for (int off = 1; off < 32; off <<= 1) {
        int u = __shfl_up_sync(0xffffffffu, v, off);
        if (lane >= off) v += u;
    }
    if (lane == 31) wt[wid] = v;
    __syncthreads();
    if (wid == 1) v += wt[0];
    if (t < nb) g_bpre[t] = v - mine;
}
__global__ void scan_phase3(int N, int E)
{
    __shared__ int warp_tot[8];
    int t = threadIdx.x;
    int lane = t & 31, wid = t >> 5;
    int base = blockIdx.x * SCAN_BLK + t * 4;
    int c[4];
    #pragma unroll
    for (int j = 0; j < 4; j++) c[j] = (base + j < N) ? g_cnt[base + j] : 0;
    int tsum = c[0] + c[1] + c[2] + c[3];
    int v = tsum;
    #pragma unroll
    for (int off = 1; off < 32; off <<= 1) {
        int u = __shfl_up_sync(0xffffffffu, v, off);
        if (lane >= off) v += u;
    }
    if (lane == 31) warp_tot[wid] = v;
    __syncthreads();
    if (wid == 0) {
        int wv = (lane < 8) ? warp_tot[lane] : 0;
        #pragma unroll
        for (int off = 1; off < 8; off <<= 1) {
            int u = __shfl_up_sync(0xffffffffu, wv, off);
            if (lane >= off) wv += u;
        }
        if (lane < 8) warp_tot[lane] = wv;
    }
    __syncthreads();
    int excl = v - tsum + ((wid > 0) ? warp_tot[wid - 1] : 0) + g_bpre[blockIdx.x];
    #pragma unroll
    for (int j = 0; j < 4; j++) {
        int idx = base + j;
        if (idx < N) { g_off[idx] = excl; g_cur[idx] = excl; }
        excl += c[j];
    }
    if (blockIdx.x == 0 && t == 0) g_off[N] = E;
}

// ---------------- K4: payload scatter (counting-sort by dst) ---------------
__global__ void scatter_sort(const int* __restrict__ ei,
                             const float* __restrict__ ew, int E)
{
    int e = blockIdx.x * blockDim.x + threadIdx.x;
    if (e >= E) return;
    int dst = ei[E + e];
    int pos = atomicAdd(&g_cur[dst], 1);
    g_edge[pos] = make_int2(ei[e], __float_as_int(ew[e]));
}

// ---------------- K5: fused gather (fp16, software-pipelined) --------------
__global__ __launch_bounds__(256) void gather_fused(float* __restrict__ out, int N)
{
    int node = (blockIdx.x * blockDim.x + threadIdx.x) >> 5;
    int lane = threadIdx.x & 31;
    if (node >= N) return;

    int beg = g_off[node];
    int end = g_off[node + 1];
    int hl = lane & 7;
    float ar = g_ar[node * HH + hl];

    float den = 0.f;
    float acc[8];
    #pragma unroll
    for (int k = 0; k < 8; k++) acc[k] = 0.f;

    int2 pc;
    uint4 qc;
    if (beg < end) {
        pc = g_edge[beg];
        qc = *(const uint4*)(g_xh + (size_t)pc.x * DD + lane * 8);
    }
    for (int i = beg; i < end; i++) {
        int2 pn; uint4 qn;
        if (i + 1 < end) {
            pn = g_edge[i + 1];
            qn = *(const uint4*)(g_xh + (size_t)pn.x * DD + lane * 8);
        }
        int src = pc.x;
        float w = __int_as_float(pc.y);
        float a = w * (g_al[src * HH + hl] + ar);
        a = fmaxf(a, 0.2f * a);                 // leaky_relu(0.2)
        float ex = __expf(a);
        den += ex;
        float coeff = __shfl_sync(0xffffffffu, ex, lane >> 2);
        const __half2* hp = (const __half2*)&qc;
        float2 f0 = __half22float2(hp[0]);
        float2 f1 = __half22float2(hp[1]);
        float2 f2 = __half22float2(hp[2]);
        float2 f3 = __half22float2(hp[3]);
        acc[0] = fmaf(coeff, f0.x, acc[0]);
        acc[1] = fmaf(coeff, f0.y, acc[1]);
        acc[2] = fmaf(coeff, f1.x, acc[2]);
        acc[3] = fmaf(coeff, f1.y, acc[3]);
        acc[4] = fmaf(coeff, f2.x, acc[4]);
        acc[5] = fmaf(coeff, f2.y, acc[5]);
        acc[6] = fmaf(coeff, f3.x, acc[6]);
        acc[7] = fmaf(coeff, f3.y, acc[7]);
        pc = pn; qc = qn;
    }

    float d = __shfl_sync(0xffffffffu, den, lane >> 2) + 1e-16f;
    float inv = 1.0f / d;

    float* o = out + (size_t)node * DD + lane * 8;   // holds residual
    float4 r0 = *(float4*)o;
    float4 r1 = *(float4*)(o + 4);
    float v;
    v = acc[0] * inv; r0.x += (v > 0.f ? v : expm1f(v));
    v = acc[1] * inv; r0.y += (v > 0.f ? v : expm1f(v));
    v = acc[2] * inv; r0.z += (v > 0.f ? v : expm1f(v));
    v = acc[3] * inv; r0.w += (v > 0.f ? v : expm1f(v));
    v = acc[4] * inv; r1.x += (v > 0.f ? v : expm1f(v));
    v = acc[5] * inv; r1.y += (v > 0.f ? v : expm1f(v));
    v = acc[6] * inv; r1.z += (v > 0.f ? v : expm1f(v));
    v = acc[7] * inv; r1.w += (v > 0.f ? v : expm1f(v));
    *(float4*)o       = r0;
    *(float4*)(o + 4) = r1;
}

// ---------------------------------------------------------------------------
extern "C" void kernel_launch(void* const* d_in, const int* in_sizes, int n_in,
                              void* d_out, int out_size)
{
    const float* feat = (const float*)d_in[0];
    const float* ew   = (const float*)d_in[1];
    const float* Wlin = (const float*)d_in[2];
    const float* attl = (const float*)d_in[3];
    const float* attr = (const float*)d_in[4];
    const float* Wres = (const float*)d_in[5];
    const int*   ei   = (const int*)d_in[6];
    float* out = (float*)d_out;

    int HC = in_sizes[3];            // 256
    int D  = in_sizes[2] / HC;       // 256
    int N  = in_sizes[0] / D;        // 50000
    int E  = in_sizes[1];            // 1600000

    static cudaStream_t s2 = nullptr;
    static cudaEvent_t evFork = nullptr, evJoin = nullptr;
    if (!s2) {
        cudaStreamCreateWithFlags(&s2, cudaStreamNonBlocking);
        cudaEventCreateWithFlags(&evFork, cudaEventDisableTiming);
        cudaEventCreateWithFlags(&evJoin, cudaEventDisableTiming);
        cudaFuncSetAttribute(gemm_tc,
                             cudaFuncAttributeMaxDynamicSharedMemorySize,
                             SMEM_GEMM);
    }

    // fork: edge chain on s2
    cudaEventRecord(evFork, 0);
    cudaStreamWaitEvent(s2, evFork, 0);

    zero_cnt<<<(N + 256) / 256, 256, 0, s2>>>(N);
    hist_dst<<<(E + 255) / 256, 256, 0, s2>>>(ei, E);
    int nb = (N + SCAN_BLK - 1) / SCAN_BLK;
    scan_phase1<<<nb, 256, 0, s2>>>(N);
    scan_phase2<<<1, 64, 0, s2>>>(nb);
    scan_phase3<<<nb, 256, 0, s2>>>(N, E);
    scatter_sort<<<(E + 255) / 256, 256, 0, s2>>>(ei, ew, E);
    cudaEventRecord(evJoin, s2);

    // main chain on default stream
    conv_feat<<<(N * (DD / 4) + 255) / 256, 256>>>(feat, N);
    conv_w<<<(NB * DD + 255) / 256, 256>>>(Wlin, Wres);

    dim3 gGemm((N + 127) / 128, 4);
    gemm_tc<<<gGemm, 256, SMEM_GEMM>>>(out, attl, attr, N);

    // join: gather needs both chains (alpha now produced inside gemm_tc)
    cudaStreamWaitEvent(0, evJoin, 0);
    gather_fused<<<(N * 32 + 255) / 256, 256>>>(out, N);
}